// round 9
// baseline (speedup 1.0000x reference)
#include <cuda_runtime.h>
#include <math.h>

#define HH   192
#define WW   192
#define CIN  64
#define SHC  8
#define NB   8
#define NPIX (HH*WW)

typedef unsigned long long ull;

// scratch for h = gelu(conv1(x)), PIXEL-MAJOR: [b][pix][8 sh-channels] (9.4 MB)
__device__ float g_h[(size_t)NB * NPIX * SHC];

__device__ __forceinline__ void cp_async4(void* dst, const void* src) {
    unsigned s = (unsigned)__cvta_generic_to_shared(dst);
    asm volatile("cp.async.ca.shared.global [%0], [%1], 4;\n" :: "r"(s), "l"(src));
}
__device__ __forceinline__ float fsqrt_approx(float v) {
    float r; asm("sqrt.approx.f32 %0, %1;" : "=f"(r) : "f"(v)); return r;
}
// ---- f32x2 packed helpers ----
__device__ __forceinline__ ull ffma2(ull a, ull b, ull c) {
    ull r; asm("fma.rn.f32x2 %0, %1, %2, %3;" : "=l"(r) : "l"(a), "l"(b), "l"(c)); return r;
}
__device__ __forceinline__ ull dup2(float v) {
    ull r; asm("mov.b64 %0, {%1, %1};" : "=l"(r) : "f"(v)); return r;
}
__device__ __forceinline__ ull pack2(float lo, float hi) {
    ull r; asm("mov.b64 %0, {%1, %2};" : "=l"(r) : "f"(lo), "f"(hi)); return r;
}
__device__ __forceinline__ void unpack2(ull v, float& lo, float& hi) {
    asm("mov.b64 {%0, %1}, %2;" : "=f"(lo), "=f"(hi) : "l"(v));
}

// ---------------------------------------------------------------------------
// Kernel 1: 3x3 SAME conv (64 -> 8) + exact GELU. (R8 version, ~88us — at its
// RF-bank/issue floor for scalar/packed FFMA.)
// ---------------------------------------------------------------------------
#define TROWS  34
#define TSTRIDE 68
#define STAGES 3

__global__ void __launch_bounds__(512, 1)
conv1_gelu_kernel(const float* __restrict__ x, const float* __restrict__ w1)
{
    __shared__ float wsm[CIN * 9 * SHC];
    __shared__ float dsm[STAGES][TROWS * TSTRIDE];

    const int tid   = threadIdx.x;
    const int b     = blockIdx.z;
    const int tileX = blockIdx.x * 64;
    const int tileY = blockIdx.y * 32;

    for (int i = tid; i < CIN * 9 * SHC; i += 512) {
        int oc  = i & 7;
        int tap = (i >> 3) % 9;
        int ic  = i / 72;
        wsm[i] = w1[(oc * CIN + ic) * 9 + tap];
    }

    const float* xb = x + (size_t)b * CIN * NPIX;

    auto load_tile = [&](int ic, int buf) {
        const float* src = xb + (size_t)ic * NPIX;
        for (int i = tid; i < TROWS * 66; i += 512) {
            int r    = i / 66;
            int ccol = i - r * 66;
            int gy   = tileY - 1 + r;
            int gx   = tileX - 1 + ccol;
            float* dp = &dsm[buf][r * TSTRIDE + ccol];
            if ((unsigned)gy < (unsigned)HH && (unsigned)gx < (unsigned)WW)
                cp_async4(dp, src + gy * WW + gx);
            else
                *dp = 0.f;
        }
    };

    load_tile(0, 0);
    asm volatile("cp.async.commit_group;\n");
    load_tile(1, 1);
    asm volatile("cp.async.commit_group;\n");

    const int tx = (tid & 15) * 4;
    const int ty = tid >> 4;

    ull acc2[4][4];
    #pragma unroll
    for (int q = 0; q < 4; q++)
        #pragma unroll
        for (int p = 0; p < 4; p++) acc2[q][p] = 0ull;

    for (int ic = 0; ic < CIN; ic++) {
        if (ic < CIN - 2) asm volatile("cp.async.wait_group 1;\n");
        else              asm volatile("cp.async.wait_group 0;\n");
        __syncthreads();
        if (ic + 2 < CIN) {
            load_tile(ic + 2, (ic + 2) % STAGES);
            asm volatile("cp.async.commit_group;\n");
        }

        const float* dd = &dsm[ic % STAGES][ty * TSTRIDE + tx];
        ull rwd[3][6];
        #pragma unroll
        for (int q = 0; q < 6; q++) {
            rwd[0][q] = dup2(dd[q]);
            rwd[1][q] = dup2(dd[TSTRIDE + q]);
            rwd[2][q] = dup2(dd[2 * TSTRIDE + q]);
        }
        const float* wp = &wsm[ic * 72];
        #pragma unroll
        for (int t = 0; t < 9; t++) {
            const int ky = t / 3, kx = t % 3;
            const ull* wq = reinterpret_cast<const ull*>(wp + t * 8);
            ull w0 = wq[0], w1q = wq[1], w2q = wq[2], w3q = wq[3];
            #pragma unroll
            for (int p = 0; p < 4; p++) {
                ull d = rwd[ky][p + kx];
                acc2[0][p] = ffma2(d, w0,  acc2[0][p]);
                acc2[1][p] = ffma2(d, w1q, acc2[1][p]);
                acc2[2][p] = ffma2(d, w2q, acc2[2][p]);
                acc2[3][p] = ffma2(d, w3q, acc2[3][p]);
            }
        }
    }

    const int gy  = tileY + ty;
    const int gx0 = tileX + tx;
    const float inv_sqrt2 = 0.70710678118654752f;
    float* hbase = g_h + ((size_t)b * NPIX + (size_t)gy * WW + gx0) * SHC;
    #pragma unroll
    for (int p = 0; p < 4; p++) {
        float v[8];
        unpack2(acc2[0][p], v[0], v[1]);
        unpack2(acc2[1][p], v[2], v[3]);
        unpack2(acc2[2][p], v[4], v[5]);
        unpack2(acc2[3][p], v[6], v[7]);
        float4 o0, o1;
        float u;
        u = v[0]; o0.x = 0.5f * u * (1.f + erff(u * inv_sqrt2));
        u = v[1]; o0.y = 0.5f * u * (1.f + erff(u * inv_sqrt2));
        u = v[2]; o0.z = 0.5f * u * (1.f + erff(u * inv_sqrt2));
        u = v[3]; o0.w = 0.5f * u * (1.f + erff(u * inv_sqrt2));
        u = v[4]; o1.x = 0.5f * u * (1.f + erff(u * inv_sqrt2));
        u = v[5]; o1.y = 0.5f * u * (1.f + erff(u * inv_sqrt2));
        u = v[6]; o1.z = 0.5f * u * (1.f + erff(u * inv_sqrt2));
        u = v[7]; o1.w = 0.5f * u * (1.f + erff(u * inv_sqrt2));
        float4* hp = reinterpret_cast<float4*>(hbase + (size_t)p * SHC);
        hp[0] = o0;
        hp[1] = o1;
    }
}

// ---------------------------------------------------------------------------
// Kernel 2: 960 threads (30 warps, reg cap 68), 1 px/iter, 5 row-phases.
// TLP replaces ILP for latency hiding; math identical to R5 fuse.
// ---------------------------------------------------------------------------
#define PAD 200

__global__ void __launch_bounds__(960, 1)
fuse_kernel(const float* __restrict__ x, const float* __restrict__ w2,
            const float* __restrict__ b2, const float* __restrict__ lsc,
            float* __restrict__ out)
{
    extern __shared__ float img[];           // NPIX + PAD floats
    const int tid  = threadIdx.x;
    const int bc   = blockIdx.x >> 1;
    const int half = blockIdx.x & 1;
    const int c    = bc & 63;

    const float4* src  = reinterpret_cast<const float4*>(x + (size_t)bc * NPIX);
    float4*       dst4 = reinterpret_cast<float4*>(img);
    for (int i = tid; i < NPIX / 4; i += 960) dst4[i] = src[i];
    if (tid < PAD / 4)
        reinterpret_cast<float4*>(img + NPIX)[tid] = make_float4(0.f, 0.f, 0.f, 0.f);

    const float PXS = 9.55f;                 // 0.1 * 95.5
    ull w01[8], w23[8];
    #pragma unroll
    for (int s = 0; s < 8; s++) {
        w01[s] = pack2(__ldg(&w2[(4 * c + 0) * 8 + s]),
                       __ldg(&w2[(4 * c + 1) * 8 + s]) * PXS);
        w23[s] = pack2(__ldg(&w2[(4 * c + 2) * 8 + s]) * PXS,
                       __ldg(&w2[(4 * c + 3) * 8 + s]));
    }
    const ull bias01 = pack2(__ldg(&b2[4 * c + 0]), __ldg(&b2[4 * c + 1]) * PXS);
    const ull bias23 = pack2(__ldg(&b2[4 * c + 2]) * PXS, __ldg(&b2[4 * c + 3]));

    const float esc   = expf(__ldg(lsc));
    const float esc4  = 0.25f * esc;
    const float esc01 = 0.1f  * esc;
    const float* hb = g_h + (size_t)(bc >> 6) * NPIX * SHC;
    float* ob = out + (size_t)bc * NPIX;

    const float step = 2.0f / 191.0f;

    const int rphase = tid / 192;            // 0..4
    const int xi     = tid - rphase * 192;   // 0..191
    const float gxpix = (fmaf((float)xi, step, -1.0f) + 1.0f) * 95.5f;
    const int ybase   = half * 96;

    __syncthreads();

    for (int yi = ybase + rphase; yi < ybase + 96; yi += 5) {
        const int   idx   = yi * WW + xi;
        const float gypix = (fmaf((float)yi, step, -1.0f) + 1.0f) * 95.5f;

        const float4* hp = reinterpret_cast<const float4*>(hb + (size_t)idx * SHC);
        float4 h0 = hp[0];
        float4 h1 = hp[1];

        ull a01 = bias01, a23 = bias23;
        {
            ull d;
            d = dup2(h0.x); a01 = ffma2(d, w01[0], a01); a23 = ffma2(d, w23[0], a23);
            d = dup2(h0.y); a01 = ffma2(d, w01[1], a01); a23 = ffma2(d, w23[1], a23);
            d = dup2(h0.z); a01 = ffma2(d, w01[2], a01); a23 = ffma2(d, w23[2], a23);
            d = dup2(h0.w); a01 = ffma2(d, w01[3], a01); a23 = ffma2(d, w23[3], a23);
            d = dup2(h1.x); a01 = ffma2(d, w01[4], a01); a23 = ffma2(d, w23[4], a23);
            d = dup2(h1.y); a01 = ffma2(d, w01[5], a01); a23 = ffma2(d, w23[5], a23);
            d = dup2(h1.z); a01 = ffma2(d, w01[6], a01); a23 = ffma2(d, w23[6], a23);
            d = dup2(h1.w); a01 = ffma2(d, w01[7], a01); a23 = ffma2(d, w23[7], a23);
        }
        float a, bxp, byp, cv;
        unpack2(a01, a, bxp);
        unpack2(a23, byp, cv);

        float t  = __expf(-fabsf(a));
        float sp = fmaxf(a, 0.f) + __logf(1.0f + t);
        float s95 = fsqrt_approx(fmaf(sp, 912.025f, 9.12025e-5f));
        cv = fminf(fmaxf(cv, -5.f), 5.f);

        float px3  = gxpix + bxp;
        float px1  = px3   + s95;
        float px2  = px3   - s95;
        float py12 = gypix + byp;
        float py3  = py12  + s95;
        float py4  = py12  - s95;

        // u1,u2 share the row
        float pyc = fminf(fmaxf(py12, 0.f), 191.f);
        float y0f = floorf(pyc);
        float wy  = pyc - y0f;

        float pxc1 = fminf(fmaxf(px1, 0.f), 191.f);
        float x0f1 = floorf(pxc1);
        float wx1  = pxc1 - x0f1;
        int   o1   = (int)fmaf(y0f, 192.f, x0f1);
        float v00 = img[o1],       v01 = img[o1 + 1];
        float v10 = img[o1 + 192], v11 = img[o1 + 193];
        float top = fmaf(v01 - v00, wx1, v00);
        float bot = fmaf(v11 - v10, wx1, v10);
        float u1  = fmaf(bot - top, wy, top);

        float pxc2 = fminf(fmaxf(px2, 0.f), 191.f);
        float x0f2 = floorf(pxc2);
        float wx2  = pxc2 - x0f2;
        int   o2   = (int)fmaf(y0f, 192.f, x0f2);
        v00 = img[o2];       v01 = img[o2 + 1];
        v10 = img[o2 + 192]; v11 = img[o2 + 193];
        top = fmaf(v01 - v00, wx2, v00);
        bot = fmaf(v11 - v10, wx2, v10);
        float u2 = fmaf(bot - top, wy, top);

        // u3,u4 share the column
        float pxc3 = fminf(fmaxf(px3, 0.f), 191.f);
        float x0f3 = floorf(pxc3);
        float wx3  = pxc3 - x0f3;

        float pyc3 = fminf(fmaxf(py3, 0.f), 191.f);
        float y0f3 = floorf(pyc3);
        float wy3  = pyc3 - y0f3;
        int   o3   = (int)fmaf(y0f3, 192.f, x0f3);
        v00 = img[o3];       v01 = img[o3 + 1];
        v10 = img[o3 + 192]; v11 = img[o3 + 193];
        top = fmaf(v01 - v00, wx3, v00);
        bot = fmaf(v11 - v10, wx3, v10);
        float u3 = fmaf(bot - top, wy3, top);

        float pyc4 = fminf(fmaxf(py4, 0.f), 191.f);
        float y0f4 = floorf(pyc4);
        float wy4  = pyc4 - y0f4;
        int   o4   = (int)fmaf(y0f4, 192.f, x0f3);
        v00 = img[o4];       v01 = img[o4 + 1];
        v10 = img[o4 + 192]; v11 = img[o4 + 193];
        top = fmaf(v01 - v00, wx3, v00);
        bot = fmaf(v11 - v10, wx3, v10);
        float u4 = fmaf(bot - top, wy4, top);

        float usum = (u1 + u2) + (u3 + u4);
        float xv   = img[idx];
        ob[idx] = fmaf(esc4, usum, esc01 * cv * xv);
    }
}

// ---------------------------------------------------------------------------
extern "C" void kernel_launch(void* const* d_in, const int* in_sizes, int n_in,
                              void* d_out, int out_size)
{
    const float *x = nullptr, *w1 = nullptr, *w2 = nullptr, *b2 = nullptr, *ls = nullptr;
    for (int i = 0; i < n_in; i++) {
        switch (in_sizes[i]) {
            case NB * CIN * NPIX: x  = (const float*)d_in[i]; break;
            case SHC * CIN * 9:   w1 = (const float*)d_in[i]; break;
            case 4 * CIN * SHC:   w2 = (const float*)d_in[i]; break;
            case 4 * CIN:         b2 = (const float*)d_in[i]; break;
            case 1:               ls = (const float*)d_in[i]; break;
            default: break;
        }
    }

    dim3 g1(3, 6, NB);                       // 64x32 tiles, 144 blocks
    conv1_gelu_kernel<<<g1, 512>>>(x, w1);

    const int smem = (NPIX + PAD) * (int)sizeof(float);
    cudaFuncSetAttribute(fuse_kernel, cudaFuncAttributeMaxDynamicSharedMemorySize, smem);
    fuse_kernel<<<NB * CIN * 2, 960, smem>>>(x, w2, b2, ls, (float*)d_out);
}

// round 10
// speedup vs baseline: 1.1157x; 1.1157x over previous
#include <cuda_runtime.h>
#include <math.h>

#define HH   192
#define WW   192
#define CIN  64
#define SHC  8
#define NB   8
#define NPIX (HH*WW)

typedef unsigned long long ull;

// scratch for h = gelu(conv1(x)), PIXEL-MAJOR: [b][pix][8 sh-channels] (9.4 MB)
__device__ float g_h[(size_t)NB * NPIX * SHC];

__device__ __forceinline__ void cp_async4(void* dst, const void* src) {
    unsigned s = (unsigned)__cvta_generic_to_shared(dst);
    asm volatile("cp.async.ca.shared.global [%0], [%1], 4;\n" :: "r"(s), "l"(src));
}
__device__ __forceinline__ float fsqrt_approx(float v) {
    float r; asm("sqrt.approx.f32 %0, %1;" : "=f"(r) : "f"(v)); return r;
}
// ---- f32x2 packed helpers (fuse coeff dot-product only) ----
__device__ __forceinline__ ull ffma2(ull a, ull b, ull c) {
    ull r; asm("fma.rn.f32x2 %0, %1, %2, %3;" : "=l"(r) : "l"(a), "l"(b), "l"(c)); return r;
}
__device__ __forceinline__ ull dup2(float v) {
    ull r; asm("mov.b64 %0, {%1, %1};" : "=l"(r) : "f"(v)); return r;
}
__device__ __forceinline__ ull pack2(float lo, float hi) {
    ull r; asm("mov.b64 %0, {%1, %2};" : "=l"(r) : "f"(lo), "f"(hi)); return r;
}
__device__ __forceinline__ void unpack2(ull v, float& lo, float& hi) {
    asm("mov.b64 {%0, %1}, %2;" : "=f"(lo), "=f"(hi) : "l"(v));
}

// ---------------------------------------------------------------------------
// Kernel 1: 3x3 SAME conv (64 -> 8) + exact GELU.
// R1 structure (measured best, ~77us = fp32 roofline): 256 threads, tile
// 64x32, scalar FFMA, 2-stage double buffer. Stores h PIXEL-MAJOR.
// ---------------------------------------------------------------------------
__global__ void __launch_bounds__(256, 1)
conv1_gelu_kernel(const float* __restrict__ x, const float* __restrict__ w1)
{
    __shared__ float wsm[CIN * 9 * SHC];     // [ic][tap][oc]
    __shared__ float dsm[2][34 * 68];        // 34 rows x 66 cols (stride 68)

    const int tid   = threadIdx.x;
    const int b     = blockIdx.z;
    const int tileX = blockIdx.x * 64;
    const int tileY = blockIdx.y * 32;

    for (int i = tid; i < CIN * 9 * SHC; i += 256) {
        int oc  = i & 7;
        int tap = (i >> 3) % 9;
        int ic  = i / 72;
        wsm[i] = w1[(oc * CIN + ic) * 9 + tap];
    }

    const float* xb = x + (size_t)b * CIN * NPIX;

    auto load_tile = [&](int ic, int buf) {
        const float* src = xb + (size_t)ic * NPIX;
        for (int i = tid; i < 34 * 66; i += 256) {
            int r    = i / 66;
            int ccol = i - r * 66;
            int gy   = tileY - 1 + r;
            int gx   = tileX - 1 + ccol;
            float* dp = &dsm[buf][r * 68 + ccol];
            if ((unsigned)gy < (unsigned)HH && (unsigned)gx < (unsigned)WW)
                cp_async4(dp, src + gy * WW + gx);
            else
                *dp = 0.f;
        }
    };

    load_tile(0, 0);
    asm volatile("cp.async.commit_group;\n");

    const int tx = (tid & 7) * 8;   // 8 threads cover 64 px
    const int ty = tid >> 3;        // 32 rows

    float acc[8][8];
    #pragma unroll
    for (int oc = 0; oc < 8; oc++)
        #pragma unroll
        for (int p = 0; p < 8; p++) acc[oc][p] = 0.f;

    for (int ic = 0; ic < CIN; ic++) {
        __syncthreads();
        if (ic + 1 < CIN) {
            load_tile(ic + 1, (ic + 1) & 1);
            asm volatile("cp.async.commit_group;\n");
            asm volatile("cp.async.wait_group 1;\n");
        } else {
            asm volatile("cp.async.wait_group 0;\n");
        }
        __syncthreads();

        const float* dd = &dsm[ic & 1][ty * 68 + tx];
        float rw[3][10];
        #pragma unroll
        for (int q = 0; q < 10; q++) {
            rw[0][q] = dd[q];
            rw[1][q] = dd[68 + q];
            rw[2][q] = dd[136 + q];
        }
        const float* wp = &wsm[ic * 72];
        #pragma unroll
        for (int ky = 0; ky < 3; ky++)
            #pragma unroll
            for (int kx = 0; kx < 3; kx++)
                #pragma unroll
                for (int oc = 0; oc < 8; oc++) {
                    float wv = wp[(ky * 3 + kx) * 8 + oc];
                    #pragma unroll
                    for (int p = 0; p < 8; p++)
                        acc[oc][p] = fmaf(rw[ky][p + kx], wv, acc[oc][p]);
                }
    }

    const int gy  = tileY + ty;
    const int gx0 = tileX + tx;
    const float inv_sqrt2 = 0.70710678118654752f;
    // pixel-major store: thread writes 8 px x 8 ch = 256B contiguous
    float* hbase = g_h + ((size_t)b * NPIX + (size_t)gy * WW + gx0) * SHC;
    #pragma unroll
    for (int p = 0; p < 8; p++) {
        float4 o0, o1;
        float u;
        u = acc[0][p]; o0.x = 0.5f * u * (1.f + erff(u * inv_sqrt2));
        u = acc[1][p]; o0.y = 0.5f * u * (1.f + erff(u * inv_sqrt2));
        u = acc[2][p]; o0.z = 0.5f * u * (1.f + erff(u * inv_sqrt2));
        u = acc[3][p]; o0.w = 0.5f * u * (1.f + erff(u * inv_sqrt2));
        u = acc[4][p]; o1.x = 0.5f * u * (1.f + erff(u * inv_sqrt2));
        u = acc[5][p]; o1.y = 0.5f * u * (1.f + erff(u * inv_sqrt2));
        u = acc[6][p]; o1.z = 0.5f * u * (1.f + erff(u * inv_sqrt2));
        u = acc[7][p]; o1.w = 0.5f * u * (1.f + erff(u * inv_sqrt2));
        float4* hp = reinterpret_cast<float4*>(hbase + (size_t)p * SHC);
        hp[0] = o0;
        hp[1] = o1;
    }
}

// ---------------------------------------------------------------------------
// Kernel 2: R5 math (best measured), 768 threads, 2-px ILP (rows y, y+48),
// 4 row-phases x 12 iterations. No prefetch (register budget 85 @ 768 thr).
// ---------------------------------------------------------------------------
#define PAD 200

__global__ void __launch_bounds__(768, 1)
fuse_kernel(const float* __restrict__ x, const float* __restrict__ w2,
            const float* __restrict__ b2, const float* __restrict__ lsc,
            float* __restrict__ out)
{
    extern __shared__ float img[];           // NPIX + PAD floats
    const int tid  = threadIdx.x;
    const int bc   = blockIdx.x >> 1;
    const int half = blockIdx.x & 1;
    const int c    = bc & 63;

    const float4* src  = reinterpret_cast<const float4*>(x + (size_t)bc * NPIX);
    float4*       dst4 = reinterpret_cast<float4*>(img);
    #pragma unroll 4
    for (int i = tid; i < NPIX / 4; i += 768) dst4[i] = src[i];
    if (tid < PAD / 4)
        reinterpret_cast<float4*>(img + NPIX)[tid] = make_float4(0.f, 0.f, 0.f, 0.f);

    const float PXS = 9.55f;                 // 0.1 * 95.5
    ull w01[8], w23[8];
    #pragma unroll
    for (int s = 0; s < 8; s++) {
        w01[s] = pack2(__ldg(&w2[(4 * c + 0) * 8 + s]),
                       __ldg(&w2[(4 * c + 1) * 8 + s]) * PXS);
        w23[s] = pack2(__ldg(&w2[(4 * c + 2) * 8 + s]) * PXS,
                       __ldg(&w2[(4 * c + 3) * 8 + s]));
    }
    const ull bias01 = pack2(__ldg(&b2[4 * c + 0]), __ldg(&b2[4 * c + 1]) * PXS);
    const ull bias23 = pack2(__ldg(&b2[4 * c + 2]) * PXS, __ldg(&b2[4 * c + 3]));

    const float esc   = expf(__ldg(lsc));
    const float esc4  = 0.25f * esc;
    const float esc01 = 0.1f  * esc;
    const float* hb = g_h + (size_t)(bc >> 6) * NPIX * SHC;
    float* ob = out + (size_t)bc * NPIX;

    const float step = 2.0f / 191.0f;

    const int rphase = tid / 192;            // 0..3
    const int xi     = tid - rphase * 192;   // 0..191
    const float gxpix = (fmaf((float)xi, step, -1.0f) + 1.0f) * 95.5f;
    const int y0     = half * 96 + rphase;

    __syncthreads();

    #pragma unroll 1
    for (int k = 0; k < 12; k++) {
        const int yiA  = y0 + 4 * k;
        const int idxA = yiA * WW + xi;

        int   idx[2]   = { idxA, idxA + 48 * WW };
        float gypix[2] = { (fmaf((float)yiA,        step, -1.0f) + 1.0f) * 95.5f,
                           (fmaf((float)(yiA + 48), step, -1.0f) + 1.0f) * 95.5f };

        // both pixels' h loads issued back-to-back (4x LDG.128)
        float4 h0[2], h1[2];
        #pragma unroll
        for (int j = 0; j < 2; j++) {
            const float4* hp = reinterpret_cast<const float4*>(hb + (size_t)idx[j] * SHC);
            h0[j] = hp[0];
            h1[j] = hp[1];
        }

        float s95[2], dxp[2], dyp[2], cvv[2];
        #pragma unroll
        for (int j = 0; j < 2; j++) {
            ull a01 = bias01, a23 = bias23;
            ull d;
            d = dup2(h0[j].x); a01 = ffma2(d, w01[0], a01); a23 = ffma2(d, w23[0], a23);
            d = dup2(h0[j].y); a01 = ffma2(d, w01[1], a01); a23 = ffma2(d, w23[1], a23);
            d = dup2(h0[j].z); a01 = ffma2(d, w01[2], a01); a23 = ffma2(d, w23[2], a23);
            d = dup2(h0[j].w); a01 = ffma2(d, w01[3], a01); a23 = ffma2(d, w23[3], a23);
            d = dup2(h1[j].x); a01 = ffma2(d, w01[4], a01); a23 = ffma2(d, w23[4], a23);
            d = dup2(h1[j].y); a01 = ffma2(d, w01[5], a01); a23 = ffma2(d, w23[5], a23);
            d = dup2(h1[j].z); a01 = ffma2(d, w01[6], a01); a23 = ffma2(d, w23[6], a23);
            d = dup2(h1[j].w); a01 = ffma2(d, w01[7], a01); a23 = ffma2(d, w23[7], a23);
            float a, bxp, byp, cv;
            unpack2(a01, a, bxp);
            unpack2(a23, byp, cv);

            float t  = __expf(-fabsf(a));
            float sp = fmaxf(a, 0.f) + __logf(1.0f + t);
            s95[j] = fsqrt_approx(fmaf(sp, 912.025f, 9.12025e-5f));
            dxp[j] = bxp;
            dyp[j] = byp;
            cvv[j] = fminf(fmaxf(cv, -5.f), 5.f);
        }

        #pragma unroll
        for (int j = 0; j < 2; j++) {
            float px3  = gxpix    + dxp[j];
            float px1  = px3      + s95[j];
            float px2  = px3      - s95[j];
            float py12 = gypix[j] + dyp[j];
            float py3  = py12     + s95[j];
            float py4  = py12     - s95[j];

            float pyc = fminf(fmaxf(py12, 0.f), 191.f);
            float y0f = floorf(pyc);
            float wy  = pyc - y0f;

            float pxc1 = fminf(fmaxf(px1, 0.f), 191.f);
            float x0f1 = floorf(pxc1);
            float wx1  = pxc1 - x0f1;
            int   o1   = (int)fmaf(y0f, 192.f, x0f1);
            float v00 = img[o1],       v01 = img[o1 + 1];
            float v10 = img[o1 + 192], v11 = img[o1 + 193];
            float top = fmaf(v01 - v00, wx1, v00);
            float bot = fmaf(v11 - v10, wx1, v10);
            float u1  = fmaf(bot - top, wy, top);

            float pxc2 = fminf(fmaxf(px2, 0.f), 191.f);
            float x0f2 = floorf(pxc2);
            float wx2  = pxc2 - x0f2;
            int   o2   = (int)fmaf(y0f, 192.f, x0f2);
            v00 = img[o2];       v01 = img[o2 + 1];
            v10 = img[o2 + 192]; v11 = img[o2 + 193];
            top = fmaf(v01 - v00, wx2, v00);
            bot = fmaf(v11 - v10, wx2, v10);
            float u2 = fmaf(bot - top, wy, top);

            float pxc3 = fminf(fmaxf(px3, 0.f), 191.f);
            float x0f3 = floorf(pxc3);
            float wx3  = pxc3 - x0f3;

            float pyc3 = fminf(fmaxf(py3, 0.f), 191.f);
            float y0f3 = floorf(pyc3);
            float wy3  = pyc3 - y0f3;
            int   o3   = (int)fmaf(y0f3, 192.f, x0f3);
            v00 = img[o3];       v01 = img[o3 + 1];
            v10 = img[o3 + 192]; v11 = img[o3 + 193];
            top = fmaf(v01 - v00, wx3, v00);
            bot = fmaf(v11 - v10, wx3, v10);
            float u3 = fmaf(bot - top, wy3, top);

            float pyc4 = fminf(fmaxf(py4, 0.f), 191.f);
            float y0f4 = floorf(pyc4);
            float wy4  = pyc4 - y0f4;
            int   o4   = (int)fmaf(y0f4, 192.f, x0f3);
            v00 = img[o4];       v01 = img[o4 + 1];
            v10 = img[o4 + 192]; v11 = img[o4 + 193];
            top = fmaf(v01 - v00, wx3, v00);
            bot = fmaf(v11 - v10, wx3, v10);
            float u4 = fmaf(bot - top, wy4, top);

            float usum = (u1 + u2) + (u3 + u4);
            float xv   = img[idx[j]];
            ob[idx[j]] = fmaf(esc4, usum, esc01 * cvv[j] * xv);
        }
    }
}

// ---------------------------------------------------------------------------
extern "C" void kernel_launch(void* const* d_in, const int* in_sizes, int n_in,
                              void* d_out, int out_size)
{
    const float *x = nullptr, *w1 = nullptr, *w2 = nullptr, *b2 = nullptr, *ls = nullptr;
    for (int i = 0; i < n_in; i++) {
        switch (in_sizes[i]) {
            case NB * CIN * NPIX: x  = (const float*)d_in[i]; break;
            case SHC * CIN * 9:   w1 = (const float*)d_in[i]; break;
            case 4 * CIN * SHC:   w2 = (const float*)d_in[i]; break;
            case 4 * CIN:         b2 = (const float*)d_in[i]; break;
            case 1:               ls = (const float*)d_in[i]; break;
            default: break;
        }
    }

    dim3 g1(3, 6, NB);                       // 64x32 tiles, 144 blocks
    conv1_gelu_kernel<<<g1, 256>>>(x, w1);

    const int smem = (NPIX + PAD) * (int)sizeof(float);
    cudaFuncSetAttribute(fuse_kernel, cudaFuncAttributeMaxDynamicSharedMemorySize, smem);
    fuse_kernel<<<NB * CIN * 2, 768, smem>>>(x, w2, b2, ls, (float*)d_out);
}